// round 13
// baseline (speedup 1.0000x reference)
#include <cuda_runtime.h>

// 2x nearest-neighbor upsample:
// in:  float32 [16, 64, 256, 256]  (1024 planes of 256x256)
// out: float32 [16, 64, 512, 512]
//
// Final probe: STG.256 (sm_100+ st.global.v8.f32) + 2-input-row vertical
// unroll. Thread idx -> (plane, hp, o8):
//   loads input rows 2hp, 2hp+1 (float4 each, independent -> MLP 2),
//   writes output rows 4hp..4hp+3, one STG.256 per row.
// Per warp: 2 x LDG.128 (512B) + 4 x STG.256 (1024B), all lane-contiguous.
// Context: all prior variants pinned at HBM ceiling (~6.68 TB/s, DRAM 84%).

#define W_IN4  64                   // float4 per input row (256/4)
#define W_OUT8 64                   // 8-float groups per output row (512/8)

__global__ void __launch_bounds__(512) upsample2x_v8x2_kernel(
    const float4* __restrict__ in4, float* __restrict__ out, int total)
{
    int idx = blockIdx.x * blockDim.x + threadIdx.x;
    if (idx >= total) return;

    // idx -> (plane, hp, o8)
    int o8    = idx & (W_OUT8 - 1);         // 0..63
    int hp    = (idx >> 6) & 127;           // 0..127 (input row pair)
    int plane = idx >> 13;                  // 0..1023

    // input float4 indices for rows 2hp, 2hp+1 at column o8
    long long ibase = ((long long)plane * 256 + 2 * hp) * W_IN4 + o8;
    float4 a = in4[ibase];                  // row 2hp
    float4 b = in4[ibase + W_IN4];          // row 2hp+1 (independent)

    // output address (floats) for row 4hp, column 8*o8
    long long obase = ((long long)plane * 512 + 4 * hp) * 512 + o8 * 8;
    float* p0 = out + obase;                // row 4hp
    float* p1 = p0 + 512;                   // row 4hp+1
    float* p2 = p0 + 1024;                  // row 4hp+2
    float* p3 = p0 + 1536;                  // row 4hp+3

    asm volatile(
        "st.global.v8.f32 [%0], {%4, %4, %5, %5, %6, %6, %7, %7};\n\t"
        "st.global.v8.f32 [%1], {%4, %4, %5, %5, %6, %6, %7, %7};\n\t"
        "st.global.v8.f32 [%2], {%8, %8, %9, %9, %10, %10, %11, %11};\n\t"
        "st.global.v8.f32 [%3], {%8, %8, %9, %9, %10, %10, %11, %11};"
        :: "l"(p0), "l"(p1), "l"(p2), "l"(p3),
           "f"(a.x), "f"(a.y), "f"(a.z), "f"(a.w),
           "f"(b.x), "f"(b.y), "f"(b.z), "f"(b.w)
        : "memory");
}

extern "C" void kernel_launch(void* const* d_in, const int* in_sizes, int n_in,
                              void* d_out, int out_size)
{
    const float4* in4 = (const float4*)d_in[0];
    float* out = (float*)d_out;

    int total = in_sizes[0] / 8;            // 8,388,608 threads (2 input rows each)
    int threads = 512;
    int blocks = (total + threads - 1) / threads;

    upsample2x_v8x2_kernel<<<blocks, threads>>>(in4, out, total);
}

// round 14
// speedup vs baseline: 1.0178x; 1.0178x over previous
#include <cuda_runtime.h>

// 2x nearest-neighbor upsample — FINAL (converged at HBM roofline):
// in:  float32 [16, 64, 256, 256]  (1024 planes of 256x256)
// out: float32 [16, 64, 512, 512]
//
// Thread indexing over OUTPUT quads (best-measured variant, R9):
//   idx -> (plane, h_in, ow4); input float2 index == idx (same linear index).
//   q = (x,x,y,y) stored to output rows 2h and 2h+1 at column ow4.
// Per warp: 1 x LDG.64 (256B contiguous) + 2 x STG.128 (512B contiguous).
// Traffic at the 1.342 GB floor; measured 6.69 TB/s (DRAM 84.3%), the
// achieved ceiling for a 1:4 read:write mixed stream on this part.
// Probed and neutral/regressive: streaming hints (R7), 2-row unroll (R8),
// STG.256 (R10), STG.256 x 2-row (R13), 256-thread blocks (R4).

#define W_OUT4 128                  // float4 per output row (512/4)

__global__ void __launch_bounds__(512) upsample2x_outidx_kernel(
    const float2* __restrict__ in2, float4* __restrict__ out4, int total)
{
    int idx = blockIdx.x * blockDim.x + threadIdx.x;
    if (idx >= total) return;

    // idx -> (plane, h, ow4); input float2 index == idx
    int ow4   = idx & (W_OUT4 - 1);         // 0..127
    int h     = (idx >> 7) & 255;           // 0..255
    int plane = idx >> 15;                  // 0..1023

    float2 v = in2[idx];
    float4 q = make_float4(v.x, v.x, v.y, v.y);

    // output row 2h of this plane, column ow4 (float4 units)
    long long base = ((long long)plane * 512 + 2 * h) * W_OUT4 + ow4;

    out4[base]          = q;   // row 2h
    out4[base + W_OUT4] = q;   // row 2h+1
}

extern "C" void kernel_launch(void* const* d_in, const int* in_sizes, int n_in,
                              void* d_out, int out_size)
{
    const float2* in2 = (const float2*)d_in[0];
    float4* out4 = (float4*)d_out;

    int total = in_sizes[0] / 2;            // 33,554,432 threads
    int threads = 512;
    int blocks = (total + threads - 1) / threads;

    upsample2x_outidx_kernel<<<blocks, threads>>>(in2, out4, total);
}